// round 1
// baseline (speedup 1.0000x reference)
#include <cuda_runtime.h>
#include <cstdint>

#define HEADS 8
#define NBAT  8
#define NTOK  1024
#define NL    3
#define CH    256
#define CPH   32              // CH/HEADS
#define RTOT  (NBAT*NTOK*NL)  // 24576 rows per stream

// ---------------- scratch (device globals: allocation-free) ----------------
// vperm[s][b][h][m][l*32+c] : per (s,b,h) a (1024 x 96) row-major matrix
__device__ float g_vperm[2u*NBAT*HEADS*NTOK*NL*CPH];   // 12.58M floats
// attout[s][b][n][l*256 + h*32 + c] : row-major (24576 x 256) per stream
__device__ float g_attout[2u*NBAT*NTOK*NL*CH];         // 12.58M floats

// ---------------- helpers ----------------
__device__ __forceinline__ uint32_t f2tf32(float x) {
    uint32_t r; asm("cvt.rna.tf32.f32 %0, %1;" : "=r"(r) : "f"(x)); return r;
}
__device__ __forceinline__ void mma8(float* d, const uint32_t* a, const uint32_t* b) {
    asm("mma.sync.aligned.m16n8k8.row.col.f32.tf32.tf32.f32 "
        "{%0,%1,%2,%3}, {%4,%5,%6,%7}, {%8,%9}, {%0,%1,%2,%3};"
        : "+f"(d[0]), "+f"(d[1]), "+f"(d[2]), "+f"(d[3])
        : "r"(a[0]), "r"(a[1]), "r"(a[2]), "r"(a[3]), "r"(b[0]), "r"(b[1]));
}
__device__ __forceinline__ void cpa16(float* smem, const float* gmem) {
    uint32_t s = (uint32_t)__cvta_generic_to_shared(smem);
    asm volatile("cp.async.cg.shared.global [%0], [%1], 16;" :: "r"(s), "l"(gmem));
}
#define CP_COMMIT() asm volatile("cp.async.commit_group;")
#define CP_WAIT(n)  asm volatile("cp.async.wait_group %0;" :: "n"(n))

// =====================================================================
// Kernel P (projection GEMM, used twice):
//   MODE 0: A = equ_s (24576x256), W = Wv  -> scatter into g_vperm
//   MODE 1: A = g_attout_s (24576x256), W = Wo -> out + residual(equ_s)
// out[r][j] = sum_k A[r][k] * W[j][k]
// Block: 128(M) x 64(N), BK=32, 8 warps as 4x2, warp = 32x32 (2x4 m16n8 tiles)
// =====================================================================
template<int MODE>
__global__ void __launch_bounds__(256) proj_kernel(
    const float* __restrict__ equ1, const float* __restrict__ equ2,
    const float* __restrict__ W, float* __restrict__ out)
{
    __shared__ float As[128*36];
    __shared__ float Ws[64*36];

    const int s = blockIdx.z;
    const float* A;
    if (MODE == 0) A = s ? equ2 : equ1;
    else           A = g_attout + (size_t)s * RTOT * CH;

    const int rbase = blockIdx.x * 128;
    const int jbase = blockIdx.y * 64;
    const int tid  = threadIdx.x;
    const int warp = tid >> 5, lane = tid & 31;
    const int wm = warp >> 1, wn = warp & 1;
    const int g = lane >> 2, tg = lane & 3;

    float acc[2][4][4];
    #pragma unroll
    for (int i = 0; i < 2; i++)
        #pragma unroll
        for (int j = 0; j < 4; j++)
            #pragma unroll
            for (int k = 0; k < 4; k++) acc[i][j][k] = 0.f;

    // per-thread load coords (constant across k-steps)
    const int ar = tid >> 3, ac4 = tid & 7;  // + t*32 rows

    for (int ks = 0; ks < CH / 32; ks++) {
        const int kb = ks * 32;
        #pragma unroll
        for (int t = 0; t < 4; t++) {
            int r = ar + t * 32;
            cpa16(&As[r*36 + ac4*4], A + (size_t)(rbase + r)*CH + kb + ac4*4);
        }
        #pragma unroll
        for (int t = 0; t < 2; t++) {
            int r = ar + t * 32;
            cpa16(&Ws[r*36 + ac4*4], W + (size_t)(jbase + r)*CH + kb + ac4*4);
        }
        CP_COMMIT(); CP_WAIT(0);
        __syncthreads();

        #pragma unroll
        for (int kk = 0; kk < 4; kk++) {
            uint32_t af[2][4];
            #pragma unroll
            for (int mi = 0; mi < 2; mi++) {
                int r = wm*32 + mi*16 + g, c = kk*8 + tg;
                af[mi][0] = f2tf32(As[r*36 + c]);
                af[mi][1] = f2tf32(As[(r+8)*36 + c]);
                af[mi][2] = f2tf32(As[r*36 + c + 4]);
                af[mi][3] = f2tf32(As[(r+8)*36 + c + 4]);
            }
            #pragma unroll
            for (int nj = 0; nj < 4; nj++) {
                int j = wn*32 + nj*8 + g, c = kk*8 + tg;
                uint32_t bf[2];
                bf[0] = f2tf32(Ws[j*36 + c]);
                bf[1] = f2tf32(Ws[j*36 + c + 4]);
                #pragma unroll
                for (int mi = 0; mi < 2; mi++) mma8(acc[mi][nj], af[mi], bf);
            }
        }
        __syncthreads();
    }

    // epilogue
    #pragma unroll
    for (int mi = 0; mi < 2; mi++)
        #pragma unroll
        for (int nj = 0; nj < 4; nj++) {
            const int j = jbase + wn*32 + nj*8 + 2*tg;
            #pragma unroll
            for (int half = 0; half < 2; half++) {
                const int r = rbase + wm*32 + mi*16 + g + half*8;
                float2 v = make_float2(acc[mi][nj][half*2], acc[mi][nj][half*2+1]);
                if (MODE == 0) {
                    int b = r / 3072, rem = r % 3072;
                    int m = rem / 3, l = rem % 3;
                    int h = j >> 5, c = j & 31;
                    size_t o = (((size_t)((s*NBAT + b)*HEADS + h)*NTOK + m)*(NL*CPH))
                               + l*CPH + c;
                    *(float2*)&g_vperm[o] = v;
                } else {
                    const float* R = s ? equ2 : equ1;
                    size_t o = (size_t)r*CH + j;
                    float2 rr = *(const float2*)&R[o];
                    v.x += rr.x; v.y += rr.y;
                    *(float2*)&out[(size_t)s*RTOT*CH + o] = v;
                }
            }
        }
}

// =====================================================================
// Kernel B (attention GEMM): per (s,b,h):
//   attout(1024 x 96) = att(1024 x 1024) @ vperm(1024 x 96)
// Block = 128(M) x 96(N), BK=32, double-buffered cp.async.
// 8 warps as 4x2; warp = 32 x 48 (2x6 m16n8 tiles).
// Grid: (8 m-tiles, 64 bh, 2 s)
// =====================================================================
__global__ void __launch_bounds__(256, 2) attn_kernel(const float* __restrict__ att)
{
    extern __shared__ float sm[];
    float* AsB = sm;                    // 2 stages * 128*36
    float* BsB = sm + 2*128*36;         // 2 stages * 32*104

    const int mt  = blockIdx.x;
    const int bh  = blockIdx.y;
    const int s   = blockIdx.z;
    const int sbh = s*64 + bh;
    const float* ap = att + (size_t)sbh * NTOK * NTOK + (size_t)mt * 128 * NTOK;
    const float* vp = g_vperm + (size_t)sbh * NTOK * (NL*CPH);

    const int tid = threadIdx.x;
    const int warp = tid >> 5, lane = tid & 31;
    const int wm = warp >> 1, wn = warp & 1;
    const int g = lane >> 2, tg = lane & 3;

    // per-thread load coords (constant)
    const int ar = tid >> 3, ac4 = tid & 7;           // att tile: rows +t*32
    int br[3], bj[3];
    #pragma unroll
    for (int t = 0; t < 3; t++) { int idx = tid + t*256; br[t] = idx / 24; bj[t] = idx % 24; }

    float acc[2][6][4];
    #pragma unroll
    for (int i = 0; i < 2; i++)
        #pragma unroll
        for (int j = 0; j < 6; j++)
            #pragma unroll
            for (int k = 0; k < 4; k++) acc[i][j][k] = 0.f;

    auto load_stage = [&](int ks, int st) {
        const int kb = ks * 32;
        float* Ad = AsB + st * (128*36);
        float* Bd = BsB + st * (32*104);
        #pragma unroll
        for (int t = 0; t < 4; t++) {
            int r = ar + t*32;
            cpa16(&Ad[r*36 + ac4*4], ap + (size_t)r*NTOK + kb + ac4*4);
        }
        #pragma unroll
        for (int t = 0; t < 3; t++)
            cpa16(&Bd[br[t]*104 + bj[t]*4], vp + (size_t)(kb + br[t])*(NL*CPH) + bj[t]*4);
        CP_COMMIT();
    };

    load_stage(0, 0);
    for (int ks = 0; ks < 32; ks++) {
        if (ks + 1 < 32) { load_stage(ks + 1, (ks + 1) & 1); CP_WAIT(1); }
        else             { CP_WAIT(0); }
        __syncthreads();

        const float* Ad = AsB + (ks & 1) * (128*36);
        const float* Bd = BsB + (ks & 1) * (32*104);
        #pragma unroll
        for (int kk = 0; kk < 4; kk++) {
            uint32_t af[2][4];
            #pragma unroll
            for (int mi = 0; mi < 2; mi++) {
                int r = wm*32 + mi*16 + g, c = kk*8 + tg;
                af[mi][0] = f2tf32(Ad[r*36 + c]);
                af[mi][1] = f2tf32(Ad[(r+8)*36 + c]);
                af[mi][2] = f2tf32(Ad[r*36 + c + 4]);
                af[mi][3] = f2tf32(Ad[(r+8)*36 + c + 4]);
            }
            #pragma unroll
            for (int nj = 0; nj < 6; nj++) {
                int j = wn*48 + nj*8 + g, c = kk*8 + tg;
                uint32_t bf[2];
                bf[0] = f2tf32(Bd[c*104 + j]);
                bf[1] = f2tf32(Bd[(c+4)*104 + j]);
                #pragma unroll
                for (int mi = 0; mi < 2; mi++) mma8(acc[mi][nj], af[mi], bf);
            }
        }
        __syncthreads();
    }

    // epilogue: scatter into attout[s][b][row][l*256 + h*32 + c]
    const int b = bh >> 3, h = bh & 7;
    float* op = g_attout + (size_t)(s*NBAT + b) * NTOK * (NL*CH);
    #pragma unroll
    for (int mi = 0; mi < 2; mi++)
        #pragma unroll
        for (int nj = 0; nj < 6; nj++) {
            const int j = wn*48 + nj*8 + 2*tg;       // 0..95 over (l,c)
            const int l = j >> 5, c = j & 31;
            #pragma unroll
            for (int half = 0; half < 2; half++) {
                const int row = mt*128 + wm*32 + mi*16 + g + half*8;
                float2 v = make_float2(acc[mi][nj][half*2], acc[mi][nj][half*2+1]);
                *(float2*)&op[(size_t)row*(NL*CH) + l*CH + h*CPH + c] = v;
            }
        }
}

// =====================================================================
extern "C" void kernel_launch(void* const* d_in, const int* in_sizes, int n_in,
                              void* d_out, int out_size)
{
    const float* att  = (const float*)d_in[0];
    const float* equ1 = (const float*)d_in[1];
    const float* equ2 = (const float*)d_in[2];
    const float* Wv   = (const float*)d_in[3];
    const float* Wo   = (const float*)d_in[4];
    float* out = (float*)d_out;

    const int SMEM_B = (2*128*36 + 2*32*104) * 4;   // 63488 bytes
    cudaFuncSetAttribute(attn_kernel, cudaFuncAttributeMaxDynamicSharedMemorySize, SMEM_B);

    // Stage 1: v = equ @ Wv^T, permuted to [s][b][h][m][l*32+c]
    proj_kernel<0><<<dim3(RTOT/128, CH/64, 2), 256>>>(equ1, equ2, Wv, nullptr);
    // Stage 2: attout = att @ v  (per b,h)
    attn_kernel<<<dim3(NTOK/128, NBAT*HEADS, 2), 256, SMEM_B>>>(att);
    // Stage 3: out = attout @ Wo^T + equ
    proj_kernel<1><<<dim3(RTOT/128, CH/64, 2), 256>>>(equ1, equ2, Wo, out);
}

// round 3
// speedup vs baseline: 1.0455x; 1.0455x over previous
#include <cuda_runtime.h>
#include <cstdint>

#define HEADS 8
#define NBAT  8
#define NTOK  1024
#define NL    3
#define CH    256
#define CPH   32
#define RTOT  (NBAT*NTOK*NL)   // 24576 rows per stream

// ---------------- scratch (device globals: allocation-free) ----------------
// vperm[s][b][h][m][l*32+c] : per (s,b,h) a (1024 x 96) [k][n] matrix, tf32-rounded
__device__ float g_vperm[2u*NBAT*HEADS*NTOK*NL*CPH];
// attout[s][b][n][l*256 + h*32 + c], tf32-rounded
__device__ float g_attout[2u*RTOT*CH];
// rounded weights: [0:64K) = Wv * 1.000339 (truncation-bias compensation), [64K:128K) = Wo
__device__ float g_W[2*CH*CH];

// ---------------- helpers ----------------
__device__ __forceinline__ uint32_t f2tf32(float x) {
    uint32_t r; asm("cvt.rna.tf32.f32 %0, %1;" : "=r"(r) : "f"(x)); return r;
}
__device__ __forceinline__ void mma8(float* d, const uint32_t* a, const uint32_t* b) {
    asm("mma.sync.aligned.m16n8k8.row.col.f32.tf32.tf32.f32 "
        "{%0,%1,%2,%3}, {%4,%5,%6,%7}, {%8,%9}, {%0,%1,%2,%3};"
        : "+f"(d[0]), "+f"(d[1]), "+f"(d[2]), "+f"(d[3])
        : "r"(a[0]), "r"(a[1]), "r"(a[2]), "r"(a[3]), "r"(b[0]), "r"(b[1]));
}
__device__ __forceinline__ void cpa16(float* smem, const float* gmem) {
    uint32_t s = (uint32_t)__cvta_generic_to_shared(smem);
    asm volatile("cp.async.cg.shared.global [%0], [%1], 16;" :: "r"(s), "l"(gmem));
}
#define CP_COMMIT() asm volatile("cp.async.commit_group;")
#define CP_WAIT(n)  asm volatile("cp.async.wait_group %0;" :: "n"(n))

// =====================================================================
// W prep: pre-round weights to tf32 so downstream raw-bit use is exact.
// Wv gets *1.000339 = 1 + 2^-11*ln2: cancels the mean truncation bias of the
// raw (RZ-truncated) uniform[0,1) attention operand in the stage-2 MMA.
// =====================================================================
__global__ void wprep_kernel(const float* __restrict__ Wv, const float* __restrict__ Wo) {
    int i = blockIdx.x * 256 + threadIdx.x;
    g_W[i]         = __uint_as_float(f2tf32(Wv[i] * 1.000339f));
    g_W[CH*CH + i] = __uint_as_float(f2tf32(Wo[i]));
}

// =====================================================================
// proj kernel: MODE 0: A=equ_s (cvt.rna), W=Wv' -> g_vperm (rounded, permuted)
//              MODE 1: A=g_attout_s (pre-rounded: raw), W=Wo' -> out + residual
// Block 128x64, BK=32, 2-stage cp.async. 8 warps as 4x2; warp 32x32.
// =====================================================================
template<int MODE>
__global__ void __launch_bounds__(256) proj_kernel(
    const float* __restrict__ equ1, const float* __restrict__ equ2,
    float* __restrict__ out)
{
    extern __shared__ float ps[];
    float* AsB = ps;                 // 2 * 128*36
    float* WsB = ps + 2*128*36;      // 2 * 64*36

    const int s = blockIdx.z;
    const float* A;
    if (MODE == 0) A = s ? equ2 : equ1;
    else           A = g_attout + (size_t)s * RTOT * CH;
    const float* W = (MODE == 0) ? g_W : (g_W + CH*CH);

    const int rbase = blockIdx.x * 128;
    const int jbase = blockIdx.y * 64;
    const int tid  = threadIdx.x;
    const int warp = tid >> 5, lane = tid & 31;
    const int wm = warp >> 1, wn = warp & 1;
    const int g = lane >> 2, tg = lane & 3;
    const int ar = tid >> 3, ac4 = tid & 7;

    float acc[2][4][4];
    #pragma unroll
    for (int i = 0; i < 2; i++)
        #pragma unroll
        for (int j = 0; j < 4; j++)
            #pragma unroll
            for (int k = 0; k < 4; k++) acc[i][j][k] = 0.f;

    auto load_stage = [&](int ks, int st) {
        const int kb = ks * 32;
        float* Ad = AsB + st * (128*36);
        float* Wd = WsB + st * (64*36);
        #pragma unroll
        for (int t = 0; t < 4; t++) {
            int r = ar + t * 32;
            cpa16(&Ad[r*36 + ac4*4], A + (size_t)(rbase + r)*CH + kb + ac4*4);
        }
        #pragma unroll
        for (int t = 0; t < 2; t++) {
            int r = ar + t * 32;
            cpa16(&Wd[r*36 + ac4*4], W + (size_t)(jbase + r)*CH + kb + ac4*4);
        }
        CP_COMMIT();
    };

    load_stage(0, 0);
    for (int ks = 0; ks < 8; ks++) {
        if (ks < 7) { load_stage(ks + 1, (ks + 1) & 1); CP_WAIT(1); }
        else        { CP_WAIT(0); }
        __syncthreads();

        const float* Ad = AsB + (ks & 1) * (128*36);
        const float* Wd = WsB + (ks & 1) * (64*36);
        #pragma unroll
        for (int kk = 0; kk < 4; kk++) {
            uint32_t af[2][4];
            #pragma unroll
            for (int mi = 0; mi < 2; mi++) {
                int r = wm*32 + mi*16 + g, c = kk*8 + tg;
                if (MODE == 0) {
                    af[mi][0] = f2tf32(Ad[r*36 + c]);
                    af[mi][1] = f2tf32(Ad[(r+8)*36 + c]);
                    af[mi][2] = f2tf32(Ad[r*36 + c + 4]);
                    af[mi][3] = f2tf32(Ad[(r+8)*36 + c + 4]);
                } else {  // pre-rounded: raw bits are exact tf32
                    af[mi][0] = __float_as_uint(Ad[r*36 + c]);
                    af[mi][1] = __float_as_uint(Ad[(r+8)*36 + c]);
                    af[mi][2] = __float_as_uint(Ad[r*36 + c + 4]);
                    af[mi][3] = __float_as_uint(Ad[(r+8)*36 + c + 4]);
                }
            }
            #pragma unroll
            for (int nj = 0; nj < 4; nj++) {
                int j = wn*32 + nj*8 + g, c = kk*8 + tg;
                uint32_t bf[2];
                bf[0] = __float_as_uint(Wd[j*36 + c]);       // W pre-rounded
                bf[1] = __float_as_uint(Wd[j*36 + c + 4]);
                #pragma unroll
                for (int mi = 0; mi < 2; mi++) mma8(acc[mi][nj], af[mi], bf);
            }
        }
        __syncthreads();
    }

    #pragma unroll
    for (int mi = 0; mi < 2; mi++)
        #pragma unroll
        for (int nj = 0; nj < 4; nj++) {
            const int j = jbase + wn*32 + nj*8 + 2*tg;
            #pragma unroll
            for (int half = 0; half < 2; half++) {
                const int r = rbase + wm*32 + mi*16 + g + half*8;
                float2 v = make_float2(acc[mi][nj][half*2], acc[mi][nj][half*2+1]);
                if (MODE == 0) {
                    // round so attn's raw-bit B operand is exact tf32
                    v.x = __uint_as_float(f2tf32(v.x));
                    v.y = __uint_as_float(f2tf32(v.y));
                    int b = r / 3072, rem = r % 3072;
                    int m = rem / 3, l = rem % 3;
                    int h = j >> 5, c = j & 31;
                    size_t o = (((size_t)((s*NBAT + b)*HEADS + h)*NTOK + m)*(NL*CPH))
                               + l*CPH + c;
                    *(float2*)&g_vperm[o] = v;
                } else {
                    const float* R = s ? equ2 : equ1;
                    size_t o = (size_t)r*CH + j;
                    float2 rr = *(const float2*)&R[o];
                    v.x += rr.x; v.y += rr.y;
                    *(float2*)&out[(size_t)s*RTOT*CH + o] = v;
                }
            }
        }
}

// =====================================================================
// attn kernel: per (s,bh,mt): attout(128 x 96) = att(128x1024) @ vperm(1024x96)
// 3-stage cp.async pipeline; raw-bit operands (no cvt in mainloop).
// att is HW-truncated (bias folded into Wv'); vperm pre-rounded (exact).
// 8 warps as 4x2; warp = 32 x 48 (2x6 m16n8 tiles).
// =====================================================================
#define A_SZ (128*36)
#define B_SZ (32*104)
#define ATTN_SMEM ((3*A_SZ + 3*B_SZ) * 4)   // 95232 B

__global__ void __launch_bounds__(256, 2) attn_kernel(const float* __restrict__ att)
{
    extern __shared__ float sm[];
    float* AsB = sm;                 // 3 stages * 128*36
    float* BsB = sm + 3*A_SZ;        // 3 stages * 32*104

    const int mt  = blockIdx.x;
    const int bh  = blockIdx.y;
    const int s   = blockIdx.z;
    const int sbh = s*64 + bh;
    const float* ap = att + (size_t)sbh * NTOK * NTOK + (size_t)mt * 128 * NTOK;
    const float* vp = g_vperm + (size_t)sbh * NTOK * (NL*CPH);

    const int tid = threadIdx.x;
    const int warp = tid >> 5, lane = tid & 31;
    const int wm = warp >> 1, wn = warp & 1;
    const int g = lane >> 2, tg = lane & 3;
    const int ar = tid >> 3, ac4 = tid & 7;
    int br[3], bj[3];
    #pragma unroll
    for (int t = 0; t < 3; t++) { int idx = tid + t*256; br[t] = idx / 24; bj[t] = idx % 24; }

    float acc[2][6][4];
    #pragma unroll
    for (int i = 0; i < 2; i++)
        #pragma unroll
        for (int j = 0; j < 6; j++)
            #pragma unroll
            for (int k = 0; k < 4; k++) acc[i][j][k] = 0.f;

    auto load_stage = [&](int ks, int st) {
        const int kb = ks * 32;
        float* Ad = AsB + st * A_SZ;
        float* Bd = BsB + st * B_SZ;
        #pragma unroll
        for (int t = 0; t < 4; t++) {
            int r = ar + t*32;
            cpa16(&Ad[r*36 + ac4*4], ap + (size_t)r*NTOK + kb + ac4*4);
        }
        #pragma unroll
        for (int t = 0; t < 3; t++)
            cpa16(&Bd[br[t]*104 + bj[t]*4], vp + (size_t)(kb + br[t])*(NL*CPH) + bj[t]*4);
        CP_COMMIT();
    };

    load_stage(0, 0);
    load_stage(1, 1);
    int st = 0;
    for (int ks = 0; ks < 32; ks++) {
        if (ks + 2 < 32) load_stage(ks + 2, (ks + 2) % 3);
        if      (ks <= 29) CP_WAIT(2);
        else if (ks == 30) CP_WAIT(1);
        else               CP_WAIT(0);
        __syncthreads();

        const float* Ad = AsB + st * A_SZ;
        const float* Bd = BsB + st * B_SZ;
        #pragma unroll
        for (int kk = 0; kk < 4; kk++) {
            uint32_t af[2][4];
            #pragma unroll
            for (int mi = 0; mi < 2; mi++) {
                int r = wm*32 + mi*16 + g, c = kk*8 + tg;
                af[mi][0] = __float_as_uint(Ad[r*36 + c]);
                af[mi][1] = __float_as_uint(Ad[(r+8)*36 + c]);
                af[mi][2] = __float_as_uint(Ad[r*36 + c + 4]);
                af[mi][3] = __float_as_uint(Ad[(r+8)*36 + c + 4]);
            }
            #pragma unroll
            for (int nj = 0; nj < 6; nj++) {
                int j = wn*48 + nj*8 + g, c = kk*8 + tg;
                uint32_t bf[2];
                bf[0] = __float_as_uint(Bd[c*104 + j]);
                bf[1] = __float_as_uint(Bd[(c+4)*104 + j]);
                #pragma unroll
                for (int mi = 0; mi < 2; mi++) mma8(acc[mi][nj], af[mi], bf);
            }
        }
        __syncthreads();
        st++; if (st == 3) st = 0;
    }

    // epilogue: round to tf32 (proj1 consumes raw bits) + scatter
    const int b = bh >> 3, h = bh & 7;
    float* op = g_attout + (size_t)(s*NBAT + b) * NTOK * (NL*CH);
    #pragma unroll
    for (int mi = 0; mi < 2; mi++)
        #pragma unroll
        for (int nj = 0; nj < 6; nj++) {
            const int j = wn*48 + nj*8 + 2*tg;
            const int l = j >> 5, c = j & 31;
            #pragma unroll
            for (int half = 0; half < 2; half++) {
                const int row = mt*128 + wm*32 + mi*16 + g + half*8;
                float2 v;
                v.x = __uint_as_float(f2tf32(acc[mi][nj][half*2]));
                v.y = __uint_as_float(f2tf32(acc[mi][nj][half*2+1]));
                *(float2*)&op[(size_t)row*(NL*CH) + l*CH + h*CPH + c] = v;
            }
        }
}

// =====================================================================
extern "C" void kernel_launch(void* const* d_in, const int* in_sizes, int n_in,
                              void* d_out, int out_size)
{
    const float* att  = (const float*)d_in[0];
    const float* equ1 = (const float*)d_in[1];
    const float* equ2 = (const float*)d_in[2];
    const float* Wv   = (const float*)d_in[3];
    const float* Wo   = (const float*)d_in[4];
    float* out = (float*)d_out;

    const int PROJ_SMEM = (2*128*36 + 2*64*36) * 4;   // 55296 B
    cudaFuncSetAttribute(proj_kernel<0>, cudaFuncAttributeMaxDynamicSharedMemorySize, PROJ_SMEM);
    cudaFuncSetAttribute(proj_kernel<1>, cudaFuncAttributeMaxDynamicSharedMemorySize, PROJ_SMEM);
    cudaFuncSetAttribute(attn_kernel, cudaFuncAttributeMaxDynamicSharedMemorySize, ATTN_SMEM);

    wprep_kernel<<<CH*CH/256, 256>>>(Wv, Wo);
    proj_kernel<0><<<dim3(RTOT/128, CH/64, 2), 256, PROJ_SMEM>>>(equ1, equ2, nullptr);
    attn_kernel<<<dim3(NTOK/128, NBAT*HEADS, 2), 256, ATTN_SMEM>>>(att);
    proj_kernel<1><<<dim3(RTOT/128, CH/64, 2), 256, PROJ_SMEM>>>(equ1, equ2, out);
}